// round 2
// baseline (speedup 1.0000x reference)
#include <cuda_runtime.h>
#include <math.h>

#define N_NODES 100000
#define N_EDGES 1600000
#define F_INDIM 128
#define AGG 48
#define FC_H 192
#define NC 10
#define SLOPE 0.2f

// ---------------- scratch (static device globals; no allocation) ----------------
__device__ float d_xl[N_NODES * AGG];
__device__ float d_xr[N_NODES * AGG];
__device__ float d_h [N_NODES * AGG];
__device__ float d_g [AGG];
__device__ int   d_deg[N_NODES];
__device__ int   d_off[N_NODES + 1];
__device__ int   d_cur[N_NODES];
__device__ int   d_eid[N_EDGES];

// ---------------- CSR build ----------------
__global__ void k_zero() {
    int i = blockIdx.x * blockDim.x + threadIdx.x;
    if (i < N_NODES) d_deg[i] = 0;
    if (i < AGG)     d_g[i] = 0.f;
}

__global__ void k_count(const int* __restrict__ dst) {
    int e = blockIdx.x * blockDim.x + threadIdx.x;
    if (e < N_EDGES) atomicAdd(&d_deg[dst[e]], 1);
}

// single-block exclusive scan over d_deg -> d_off, d_cur ; d_off[N]=E
__global__ void k_scan() {
    __shared__ int wsum[32];
    __shared__ int carry;
    int t = threadIdx.x, lane = t & 31, w = t >> 5;
    if (t == 0) carry = 0;
    __syncthreads();
    for (int base = 0; base < N_NODES; base += 1024) {
        int i = base + t;
        int v = (i < N_NODES) ? d_deg[i] : 0;
        int x = v;
        #pragma unroll
        for (int o = 1; o < 32; o <<= 1) {
            int y = __shfl_up_sync(0xffffffffu, x, o);
            if (lane >= o) x += y;
        }
        if (lane == 31) wsum[w] = x;
        __syncthreads();
        if (w == 0) {
            int s = wsum[lane];
            #pragma unroll
            for (int o = 1; o < 32; o <<= 1) {
                int y = __shfl_up_sync(0xffffffffu, s, o);
                if (lane >= o) s += y;
            }
            wsum[lane] = s;
        }
        __syncthreads();
        int incl = x + (w > 0 ? wsum[w - 1] : 0) + carry;
        if (i < N_NODES) { d_off[i] = incl - v; d_cur[i] = incl - v; }
        __syncthreads();
        if (t == 1023) carry = incl;
        __syncthreads();
    }
    if (t == 0) d_off[N_NODES] = carry;
}

__global__ void k_scatter(const int* __restrict__ dst) {
    int e = blockIdx.x * blockDim.x + threadIdx.x;
    if (e < N_EDGES) {
        int p = atomicAdd(&d_cur[dst[e]], 1);
        d_eid[p] = e;
    }
}

// ---------------- fused node-wise linears: xl = h@Wl.T+bl, xr = h@Wr.T+br ----------------
// warp per node; weights transposed into shared as Ws[k][c] (conflict-free across c).
// Reads each node's feature row ONCE for both transforms.
__global__ void k_gemm2(const float* __restrict__ hin_ext, int use_h, int D,
                        const float* __restrict__ Wl, const float* __restrict__ bl,
                        const float* __restrict__ Wr, const float* __restrict__ br) {
    __shared__ float WsL[F_INDIM * AGG];  // 24KB
    __shared__ float WsR[F_INDIM * AGG];  // 24KB  (48KB total = static smem limit)
    const float* hin = use_h ? d_h : hin_ext;

    int tot = D * AGG;
    for (int j = threadIdx.x; j < tot; j += blockDim.x) {
        int c = j / D, k = j % D;          // W row-major [AGG][D], j = c*D + k
        WsL[k * AGG + c] = Wl[j];
        WsR[k * AGG + c] = Wr[j];
    }
    __syncthreads();

    int warp = threadIdx.x >> 5, lane = threadIdx.x & 31;
    int node = blockIdx.x * 8 + warp;
    if (node >= N_NODES) return;

    int c0 = lane, c1 = lane + 32;
    bool has1 = (c1 < AGG);
    float al0 = bl[c0], ar0 = br[c0];
    float al1 = has1 ? bl[c1] : 0.f;
    float ar1 = has1 ? br[c1] : 0.f;
    const float* hp = hin + (size_t)node * D;
    #pragma unroll 4
    for (int k = 0; k < D; k++) {
        float hk = __ldg(&hp[k]);   // broadcast load
        al0 = fmaf(hk, WsL[k * AGG + c0], al0);
        ar0 = fmaf(hk, WsR[k * AGG + c0], ar0);
        if (has1) {
            al1 = fmaf(hk, WsL[k * AGG + c1], al1);
            ar1 = fmaf(hk, WsR[k * AGG + c1], ar1);
        }
    }
    d_xl[node * AGG + c0] = al0;
    d_xr[node * AGG + c0] = ar0;
    if (has1) {
        d_xl[node * AGG + c1] = al1;
        d_xr[node * AGG + c1] = ar1;
    }
}

// ---------------- GATv2 aggregation: warp per dst node, online softmax ----------------
// fuse_readout: last layer also accumulates the global sum-readout into d_g.
__global__ void k_agg(const int* __restrict__ srcArr, const float* __restrict__ ea,
                      const float* __restrict__ We, const float* __restrict__ att,
                      const float* __restrict__ bias, int fuse_readout) {
    __shared__ float sWeT[4 * AGG];  // sWeT[d*AGG + c] = We[c*4 + d]
    __shared__ float sAtt[AGG];
    __shared__ float sB[AGG];
    __shared__ float sG[AGG];
    int t = threadIdx.x;
    if (t < 4 * AGG) {
        int d = t / AGG, c = t % AGG;
        sWeT[t] = We[c * 4 + d];
    }
    if (t < AGG) { sAtt[t] = att[t]; sB[t] = bias[t]; sG[t] = 0.f; }
    __syncthreads();

    int warp = t >> 5, lane = t & 31;
    int v = blockIdx.x * 8 + warp;
    if (v < N_NODES) {
        int c0 = lane, c1 = lane + 32;
        bool has1 = (c1 < AGG);
        float xr0 = d_xr[v * AGG + c0];
        float xr1 = has1 ? d_xr[v * AGG + c1] : 0.f;
        float a0 = sAtt[c0];
        float a1 = has1 ? sAtt[c1] : 0.f;
        float w00 = sWeT[0 * AGG + c0], w10 = sWeT[1 * AGG + c0],
              w20 = sWeT[2 * AGG + c0], w30 = sWeT[3 * AGG + c0];
        float w01 = 0.f, w11 = 0.f, w21 = 0.f, w31 = 0.f;
        if (has1) {
            w01 = sWeT[0 * AGG + c1]; w11 = sWeT[1 * AGG + c1];
            w21 = sWeT[2 * AGG + c1]; w31 = sWeT[3 * AGG + c1];
        }

        float M = -INFINITY, den = 0.f, acc0 = 0.f, acc1 = 0.f;
        int beg = d_off[v], end = d_off[v + 1];
        for (int i = beg; i < end; i++) {
            int eid = __ldg(&d_eid[i]);
            int u   = __ldg(&srcArr[eid]);
            float4 e4 = __ldg(((const float4*)ea) + eid);

            float xl0 = __ldg(&d_xl[u * AGG + c0]);
            float m0 = xl0 + xr0 + e4.x * w00 + e4.y * w10 + e4.z * w20 + e4.w * w30;
            float lr0 = fmaxf(m0, SLOPE * m0);
            float part = a0 * lr0;

            float xl1 = 0.f;
            if (has1) {
                xl1 = __ldg(&d_xl[u * AGG + c1]);
                float m1 = xl1 + xr1 + e4.x * w01 + e4.y * w11 + e4.z * w21 + e4.w * w31;
                float lr1 = fmaxf(m1, SLOPE * m1);
                part += a1 * lr1;
            }
            #pragma unroll
            for (int o = 16; o > 0; o >>= 1)
                part += __shfl_xor_sync(0xffffffffu, part, o);
            float e = part;   // attention logit (uniform across warp)

            float newM = fmaxf(M, e);
            float s = __expf(M - newM);     // 0 on first edge
            float p = __expf(e - newM);
            den  = den  * s + p;
            acc0 = acc0 * s + p * xl0;
            acc1 = acc1 * s + p * xl1;
            M = newM;
        }
        float inv = 1.f / fmaxf(den, 1e-16f);
        float o0 = fmaxf(fmaf(acc0, inv, sB[c0]), 0.f);
        d_h[v * AGG + c0] = o0;
        float o1 = 0.f;
        if (has1) {
            o1 = fmaxf(fmaf(acc1, inv, sB[c1]), 0.f);
            d_h[v * AGG + c1] = o1;
        }
        if (fuse_readout) {
            atomicAdd(&sG[c0], o0);
            if (has1) atomicAdd(&sG[c1], o1);
        }
    }
    if (fuse_readout) {
        __syncthreads();
        if (t < AGG) atomicAdd(&d_g[t], sG[t]);
    }
}

// ---------------- MLP head + softmax ----------------
__global__ void k_mlp(const float* __restrict__ fc1w, const float* __restrict__ fc1b,
                      const float* __restrict__ fc2w, const float* __restrict__ fc2b,
                      float* __restrict__ out) {
    __shared__ float sg[AGG];
    __shared__ float sf[FC_H];
    __shared__ float sl[NC];
    int t = threadIdx.x;
    if (t < AGG) sg[t] = d_g[t];
    __syncthreads();
    if (t < FC_H) {
        float s = fc1b[t];
        #pragma unroll 8
        for (int k = 0; k < AGG; k++) s = fmaf(sg[k], fc1w[t * AGG + k], s);
        sf[t] = fmaxf(s, 0.f);
    }
    __syncthreads();
    if (t < NC) {
        float s = fc2b[t];
        for (int k = 0; k < FC_H; k++) s = fmaf(sf[k], fc2w[t * FC_H + k], s);
        sl[t] = s;
    }
    __syncthreads();
    if (t == 0) {
        float mx = sl[0];
        for (int i = 1; i < NC; i++) mx = fmaxf(mx, sl[i]);
        float sum = 0.f, ex[NC];
        for (int i = 0; i < NC; i++) { ex[i] = expf(sl[i] - mx); sum += ex[i]; }
        for (int i = 0; i < NC; i++) out[i] = ex[i] / sum;
    }
}

// ---------------- launch ----------------
extern "C" void kernel_launch(void* const* d_in, const int* in_sizes, int n_in,
                              void* d_out, int out_size) {
    const float* x   = (const float*)d_in[0];
    const int*   ei  = (const int*)d_in[1];
    const int*   src = ei;
    const int*   dst = ei + N_EDGES;
    const float* ea  = (const float*)d_in[2];

    const float *Wl[3], *bl[3], *Wr[3], *br[3], *We[3], *att[3], *bb[3];
    for (int l = 0; l < 3; l++) {
        int base = 3 + l * 7;
        Wl[l]  = (const float*)d_in[base + 0];
        bl[l]  = (const float*)d_in[base + 1];
        Wr[l]  = (const float*)d_in[base + 2];
        br[l]  = (const float*)d_in[base + 3];
        We[l]  = (const float*)d_in[base + 4];
        att[l] = (const float*)d_in[base + 5];
        bb[l]  = (const float*)d_in[base + 6];
    }
    const float* fc1w = (const float*)d_in[24];
    const float* fc1b = (const float*)d_in[25];
    const float* fc2w = (const float*)d_in[26];
    const float* fc2b = (const float*)d_in[27];
    float* out = (float*)d_out;

    k_zero   <<<(N_NODES + 255) / 256, 256>>>();
    k_count  <<<(N_EDGES + 255) / 256, 256>>>(dst);
    k_scan   <<<1, 1024>>>();
    k_scatter<<<(N_EDGES + 255) / 256, 256>>>(dst);

    int gb = (N_NODES + 7) / 8;
    for (int l = 0; l < 3; l++) {
        int D = (l == 0) ? F_INDIM : AGG;
        k_gemm2<<<gb, 256>>>(x, (l > 0) ? 1 : 0, D, Wl[l], bl[l], Wr[l], br[l]);
        k_agg  <<<gb, 256>>>(src, ea, We[l], att[l], bb[l], (l == 2) ? 1 : 0);
    }

    k_mlp<<<1, 192>>>(fc1w, fc1b, fc2w, fc2b, out);
}

// round 4
// speedup vs baseline: 1.9091x; 1.9091x over previous
#include <cuda_runtime.h>
#include <math.h>

#define N_NODES 100000
#define N_EDGES 1600000
#define F_INDIM 128
#define AGG 48
#define FC_H 192
#define NC 10
#define SLOPE 0.2f

// ---------------- scratch (static device globals; no allocation) ----------------
__device__ float  d_xl[N_NODES * AGG];
__device__ float  d_xr[N_NODES * AGG];
__device__ float  d_h [N_NODES * AGG];
__device__ float  d_g [AGG];
__device__ int    d_deg[N_NODES];
__device__ int    d_off[N_NODES + 1];
__device__ int    d_cur[N_NODES];
__device__ int    d_srcs[N_EDGES];     // src node ids, sorted by dst (CSR order)
__device__ float4 d_eas[N_EDGES];      // edge attrs, sorted by dst (CSR order)

// ---------------- CSR build ----------------
__global__ void k_zero() {
    int i = blockIdx.x * blockDim.x + threadIdx.x;
    if (i < N_NODES) d_deg[i] = 0;
    if (i < AGG)     d_g[i] = 0.f;
}

__global__ void k_count(const int* __restrict__ dst) {
    int e = blockIdx.x * blockDim.x + threadIdx.x;
    if (e < N_EDGES) atomicAdd(&d_deg[dst[e]], 1);
}

// single-block exclusive scan over d_deg -> d_off, d_cur ; d_off[N]=E
__global__ void k_scan() {
    __shared__ int wsum[32];
    __shared__ int carry;
    int t = threadIdx.x, lane = t & 31, w = t >> 5;
    if (t == 0) carry = 0;
    __syncthreads();
    for (int base = 0; base < N_NODES; base += 1024) {
        int i = base + t;
        int v = (i < N_NODES) ? d_deg[i] : 0;
        int x = v;
        #pragma unroll
        for (int o = 1; o < 32; o <<= 1) {
            int y = __shfl_up_sync(0xffffffffu, x, o);
            if (lane >= o) x += y;
        }
        if (lane == 31) wsum[w] = x;
        __syncthreads();
        if (w == 0) {
            int s = wsum[lane];
            #pragma unroll
            for (int o = 1; o < 32; o <<= 1) {
                int y = __shfl_up_sync(0xffffffffu, s, o);
                if (lane >= o) s += y;
            }
            wsum[lane] = s;
        }
        __syncthreads();
        int incl = x + (w > 0 ? wsum[w - 1] : 0) + carry;
        if (i < N_NODES) { d_off[i] = incl - v; d_cur[i] = incl - v; }
        __syncthreads();
        if (t == 1023) carry = incl;
        __syncthreads();
    }
    if (t == 0) d_off[N_NODES] = carry;
}

// scatter edges into CSR order, pre-gathering src id and edge attr
__global__ void k_scatter(const int* __restrict__ src, const int* __restrict__ dst,
                          const float4* __restrict__ ea) {
    int e = blockIdx.x * blockDim.x + threadIdx.x;
    if (e < N_EDGES) {
        int p = atomicAdd(&d_cur[dst[e]], 1);
        d_srcs[p] = src[e];
        d_eas[p]  = ea[e];
    }
}

// ---------------- fused node-wise linears: xl = h@Wl.T+bl, xr = h@Wr.T+br ----------------
// Register-tiled: thread = 2 nodes x 4 channels. 240 active threads = 20 node-pairs = 40 nodes/block.
__global__ void k_gemm2(const float* __restrict__ hin_ext, int use_h, int D,
                        const float* __restrict__ Wl, const float* __restrict__ bl,
                        const float* __restrict__ Wr, const float* __restrict__ br) {
    __shared__ float WsL[F_INDIM * AGG];  // transposed: Ws[k*48 + c]
    __shared__ float WsR[F_INDIM * AGG];
    const float* hin = use_h ? d_h : hin_ext;

    int t = threadIdx.x;
    int tot = D * AGG;
    for (int j = t; j < tot; j += blockDim.x) {
        int c = j / D, k = j % D;          // W row-major [AGG][D]
        WsL[k * AGG + c] = Wl[j];
        WsR[k * AGG + c] = Wr[j];
    }
    __syncthreads();
    if (t >= 240) return;

    int cg = t % 12;            // channel float4 group: channels cg*4..cg*4+3
    int pair = t / 12;          // 0..19
    int n0 = blockIdx.x * 40 + pair * 2;
    int n1 = n0 + 1;

    float4 bL = ((const float4*)bl)[cg];
    float4 bR = ((const float4*)br)[cg];
    float4 aL0 = bL, aR0 = bR, aL1 = bL, aR1 = bR;

    const float* hp0 = hin + (size_t)n0 * D;
    const float* hp1 = hin + (size_t)n1 * D;

    for (int k = 0; k < D; k += 4) {
        float4 h0 = *(const float4*)(hp0 + k);
        float4 h1 = *(const float4*)(hp1 + k);
        float ha[4] = {h0.x, h0.y, h0.z, h0.w};
        float hb[4] = {h1.x, h1.y, h1.z, h1.w};
        #pragma unroll
        for (int j = 0; j < 4; j++) {
            float4 wl = *(const float4*)&WsL[(k + j) * AGG + cg * 4];
            float4 wr = *(const float4*)&WsR[(k + j) * AGG + cg * 4];
            aL0.x = fmaf(ha[j], wl.x, aL0.x); aL0.y = fmaf(ha[j], wl.y, aL0.y);
            aL0.z = fmaf(ha[j], wl.z, aL0.z); aL0.w = fmaf(ha[j], wl.w, aL0.w);
            aR0.x = fmaf(ha[j], wr.x, aR0.x); aR0.y = fmaf(ha[j], wr.y, aR0.y);
            aR0.z = fmaf(ha[j], wr.z, aR0.z); aR0.w = fmaf(ha[j], wr.w, aR0.w);
            aL1.x = fmaf(hb[j], wl.x, aL1.x); aL1.y = fmaf(hb[j], wl.y, aL1.y);
            aL1.z = fmaf(hb[j], wl.z, aL1.z); aL1.w = fmaf(hb[j], wl.w, aL1.w);
            aR1.x = fmaf(hb[j], wr.x, aR1.x); aR1.y = fmaf(hb[j], wr.y, aR1.y);
            aR1.z = fmaf(hb[j], wr.z, aR1.z); aR1.w = fmaf(hb[j], wr.w, aR1.w);
        }
    }
    ((float4*)d_xl)[n0 * 12 + cg] = aL0;
    ((float4*)d_xr)[n0 * 12 + cg] = aR0;
    ((float4*)d_xl)[n1 * 12 + cg] = aL1;
    ((float4*)d_xr)[n1 * 12 + cg] = aR1;
}

// ---------------- GATv2 aggregation: warp per dst node, halves split edges ----------------
// Lanes: half = lane>>4, L = lane&15; lanes L<12 hold channels [L*4, L*4+4).
// Each half-warp processes every other CSR edge of node v (stride 2), online softmax.
// NOTE: halves may diverge (different trip counts) -> all in-loop shuffles use the
// HALF-WARP mask (offsets 8..1 never cross the 16-lane boundary). The final merge
// (offset 16) runs after __syncwarp() with the full mask.
__global__ void k_agg(const float* __restrict__ We, const float* __restrict__ att,
                      const float* __restrict__ bias, int fuse_readout) {
    __shared__ float sG[AGG];
    int t = threadIdx.x;
    if (t < AGG) sG[t] = 0.f;
    __syncthreads();

    int warp = t >> 5, lane = t & 31;
    int half = lane >> 4, L = lane & 15;
    unsigned hmask = 0xFFFFu << (half * 16);
    bool active = (L < 12);
    int v = blockIdx.x * 8 + warp;

    float M = -INFINITY, den = 0.f;
    float4 acc = make_float4(0, 0, 0, 0);
    float4 b4 = make_float4(0, 0, 0, 0);
    bool valid = (v < N_NODES);

    if (valid) {
        float4 xr4  = active ? ((const float4*)d_xr)[v * 12 + L] : make_float4(0, 0, 0, 0);
        float4 a4   = active ? __ldg(((const float4*)att) + L)   : make_float4(0, 0, 0, 0);
        b4          = active ? __ldg(((const float4*)bias) + L)  : make_float4(0, 0, 0, 0);
        float4 W0, W1, W2, W3;
        if (active) {
            int c4 = L * 4;
            W0 = __ldg(((const float4*)We) + c4 + 0);
            W1 = __ldg(((const float4*)We) + c4 + 1);
            W2 = __ldg(((const float4*)We) + c4 + 2);
            W3 = __ldg(((const float4*)We) + c4 + 3);
        } else {
            W0 = W1 = W2 = W3 = make_float4(0, 0, 0, 0);
        }

        int beg = d_off[v], end = d_off[v + 1];
        int i = beg + half;

        // 2-edge unrolled main loop (edges i and i+2 for this half)
        for (; i + 2 < end; i += 4) {
            int u1 = __ldg(&d_srcs[i]);
            int u2 = __ldg(&d_srcs[i + 2]);
            float4 e1 = __ldg(&d_eas[i]);
            float4 e2 = __ldg(&d_eas[i + 2]);
            float4 x1 = active ? __ldg(((const float4*)d_xl) + u1 * 12 + L) : make_float4(0, 0, 0, 0);
            float4 x2 = active ? __ldg(((const float4*)d_xl) + u2 * 12 + L) : make_float4(0, 0, 0, 0);

            float4 m1, m2;
            m1.x = x1.x + xr4.x + e1.x * W0.x + e1.y * W0.y + e1.z * W0.z + e1.w * W0.w;
            m1.y = x1.y + xr4.y + e1.x * W1.x + e1.y * W1.y + e1.z * W1.z + e1.w * W1.w;
            m1.z = x1.z + xr4.z + e1.x * W2.x + e1.y * W2.y + e1.z * W2.z + e1.w * W2.w;
            m1.w = x1.w + xr4.w + e1.x * W3.x + e1.y * W3.y + e1.z * W3.z + e1.w * W3.w;
            m2.x = x2.x + xr4.x + e2.x * W0.x + e2.y * W0.y + e2.z * W0.z + e2.w * W0.w;
            m2.y = x2.y + xr4.y + e2.x * W1.x + e2.y * W1.y + e2.z * W1.z + e2.w * W1.w;
            m2.z = x2.z + xr4.z + e2.x * W2.x + e2.y * W2.y + e2.z * W2.z + e2.w * W2.w;
            m2.w = x2.w + xr4.w + e2.x * W3.x + e2.y * W3.y + e2.z * W3.z + e2.w * W3.w;

            float p1 = a4.x * fmaxf(m1.x, SLOPE * m1.x) + a4.y * fmaxf(m1.y, SLOPE * m1.y)
                     + a4.z * fmaxf(m1.z, SLOPE * m1.z) + a4.w * fmaxf(m1.w, SLOPE * m1.w);
            float p2 = a4.x * fmaxf(m2.x, SLOPE * m2.x) + a4.y * fmaxf(m2.y, SLOPE * m2.y)
                     + a4.z * fmaxf(m2.z, SLOPE * m2.z) + a4.w * fmaxf(m2.w, SLOPE * m2.w);
            #pragma unroll
            for (int o = 8; o > 0; o >>= 1) {
                p1 += __shfl_xor_sync(hmask, p1, o);
                p2 += __shfl_xor_sync(hmask, p2, o);
            }
            float nM = fmaxf(M, fmaxf(p1, p2));
            float s  = __expf(M - nM);           // 0 when M=-inf (nM finite)
            float w1 = __expf(p1 - nM);
            float w2 = __expf(p2 - nM);
            den   = den * s + w1 + w2;
            acc.x = acc.x * s + w1 * x1.x + w2 * x2.x;
            acc.y = acc.y * s + w1 * x1.y + w2 * x2.y;
            acc.z = acc.z * s + w1 * x1.z + w2 * x2.z;
            acc.w = acc.w * s + w1 * x1.w + w2 * x2.w;
            M = nM;
        }
        // remainder (at most one edge per half)
        for (; i < end; i += 2) {
            int u1 = __ldg(&d_srcs[i]);
            float4 e1 = __ldg(&d_eas[i]);
            float4 x1 = active ? __ldg(((const float4*)d_xl) + u1 * 12 + L) : make_float4(0, 0, 0, 0);
            float4 m1;
            m1.x = x1.x + xr4.x + e1.x * W0.x + e1.y * W0.y + e1.z * W0.z + e1.w * W0.w;
            m1.y = x1.y + xr4.y + e1.x * W1.x + e1.y * W1.y + e1.z * W1.z + e1.w * W1.w;
            m1.z = x1.z + xr4.z + e1.x * W2.x + e1.y * W2.y + e1.z * W2.z + e1.w * W2.w;
            m1.w = x1.w + xr4.w + e1.x * W3.x + e1.y * W3.y + e1.z * W3.z + e1.w * W3.w;
            float p1 = a4.x * fmaxf(m1.x, SLOPE * m1.x) + a4.y * fmaxf(m1.y, SLOPE * m1.y)
                     + a4.z * fmaxf(m1.z, SLOPE * m1.z) + a4.w * fmaxf(m1.w, SLOPE * m1.w);
            #pragma unroll
            for (int o = 8; o > 0; o >>= 1)
                p1 += __shfl_xor_sync(hmask, p1, o);
            float nM = fmaxf(M, p1);
            float s  = __expf(M - nM);
            float w1 = __expf(p1 - nM);
            den   = den * s + w1;
            acc.x = acc.x * s + w1 * x1.x;
            acc.y = acc.y * s + w1 * x1.y;
            acc.z = acc.z * s + w1 * x1.z;
            acc.w = acc.w * s + w1 * x1.w;
            M = nM;
        }
    }

    // reconverge the whole warp, then merge the two halves' states
    __syncwarp();
    float Mo   = __shfl_xor_sync(0xffffffffu, M,   16);
    float deno = __shfl_xor_sync(0xffffffffu, den, 16);
    float4 aco;
    aco.x = __shfl_xor_sync(0xffffffffu, acc.x, 16);
    aco.y = __shfl_xor_sync(0xffffffffu, acc.y, 16);
    aco.z = __shfl_xor_sync(0xffffffffu, acc.z, 16);
    aco.w = __shfl_xor_sync(0xffffffffu, acc.w, 16);

    if (valid) {
        float nM = fmaxf(M, Mo);
        if (nM > -INFINITY) {
            float s  = __expf(M - nM);
            float so = __expf(Mo - nM);
            den   = den * s + deno * so;
            acc.x = acc.x * s + aco.x * so;
            acc.y = acc.y * s + aco.y * so;
            acc.z = acc.z * s + aco.z * so;
            acc.w = acc.w * s + aco.w * so;
        }   // else: no edges at all -> den=0, acc=0

        float inv = 1.f / fmaxf(den, 1e-16f);
        float4 out;
        out.x = fmaxf(fmaf(acc.x, inv, b4.x), 0.f);
        out.y = fmaxf(fmaf(acc.y, inv, b4.y), 0.f);
        out.z = fmaxf(fmaf(acc.z, inv, b4.z), 0.f);
        out.w = fmaxf(fmaf(acc.w, inv, b4.w), 0.f);

        if (half == 0 && active) {
            ((float4*)d_h)[v * 12 + L] = out;
            if (fuse_readout) {
                int c4 = L * 4;
                atomicAdd(&sG[c4 + 0], out.x);
                atomicAdd(&sG[c4 + 1], out.y);
                atomicAdd(&sG[c4 + 2], out.z);
                atomicAdd(&sG[c4 + 3], out.w);
            }
        }
    }
    if (fuse_readout) {
        __syncthreads();
        if (t < AGG) atomicAdd(&d_g[t], sG[t]);
    }
}

// ---------------- MLP head + softmax ----------------
__global__ void k_mlp(const float* __restrict__ fc1w, const float* __restrict__ fc1b,
                      const float* __restrict__ fc2w, const float* __restrict__ fc2b,
                      float* __restrict__ out) {
    __shared__ float sg[AGG];
    __shared__ float sf[FC_H];
    __shared__ float sl[NC];
    int t = threadIdx.x;
    if (t < AGG) sg[t] = d_g[t];
    __syncthreads();
    if (t < FC_H) {
        float s = fc1b[t];
        #pragma unroll 8
        for (int k = 0; k < AGG; k++) s = fmaf(sg[k], fc1w[t * AGG + k], s);
        sf[t] = fmaxf(s, 0.f);
    }
    __syncthreads();
    if (t < NC) {
        float s = fc2b[t];
        for (int k = 0; k < FC_H; k++) s = fmaf(sf[k], fc2w[t * FC_H + k], s);
        sl[t] = s;
    }
    __syncthreads();
    if (t == 0) {
        float mx = sl[0];
        for (int i = 1; i < NC; i++) mx = fmaxf(mx, sl[i]);
        float sum = 0.f, ex[NC];
        for (int i = 0; i < NC; i++) { ex[i] = expf(sl[i] - mx); sum += ex[i]; }
        for (int i = 0; i < NC; i++) out[i] = ex[i] / sum;
    }
}

// ---------------- launch ----------------
extern "C" void kernel_launch(void* const* d_in, const int* in_sizes, int n_in,
                              void* d_out, int out_size) {
    const float* x   = (const float*)d_in[0];
    const int*   ei  = (const int*)d_in[1];
    const int*   src = ei;
    const int*   dst = ei + N_EDGES;
    const float* ea  = (const float*)d_in[2];

    const float *Wl[3], *bl[3], *Wr[3], *br[3], *We[3], *att[3], *bb[3];
    for (int l = 0; l < 3; l++) {
        int base = 3 + l * 7;
        Wl[l]  = (const float*)d_in[base + 0];
        bl[l]  = (const float*)d_in[base + 1];
        Wr[l]  = (const float*)d_in[base + 2];
        br[l]  = (const float*)d_in[base + 3];
        We[l]  = (const float*)d_in[base + 4];
        att[l] = (const float*)d_in[base + 5];
        bb[l]  = (const float*)d_in[base + 6];
    }
    const float* fc1w = (const float*)d_in[24];
    const float* fc1b = (const float*)d_in[25];
    const float* fc2w = (const float*)d_in[26];
    const float* fc2b = (const float*)d_in[27];
    float* out = (float*)d_out;

    k_zero   <<<(N_NODES + 255) / 256, 256>>>();
    k_count  <<<(N_EDGES + 255) / 256, 256>>>(dst);
    k_scan   <<<1, 1024>>>();
    k_scatter<<<(N_EDGES + 255) / 256, 256>>>(src, dst, (const float4*)ea);

    for (int l = 0; l < 3; l++) {
        int D = (l == 0) ? F_INDIM : AGG;
        k_gemm2<<<N_NODES / 40, 256>>>(x, (l > 0) ? 1 : 0, D, Wl[l], bl[l], Wr[l], br[l]);
        k_agg  <<<(N_NODES + 7) / 8, 256>>>(We[l], att[l], bb[l], (l == 2) ? 1 : 0);
    }

    k_mlp<<<1, 192>>>(fc1w, fc1b, fc2w, fc2b, out);
}